// round 12
// baseline (speedup 1.0000x reference)
#include <cuda_runtime.h>
#include <cuda_bf16.h>
#include <cstdint>

// ---------------------------------------------------------------------------
// GeometricTerm: algebraic collapse + HMMA (mma.sync bf16x3) GEMM chain.
//   geo[nk,h,w] = Gx[nk,h] + Gy[nk,w]
// 5 launches: emb_all -> {hmma_v | img} -> reduce_v -> hmma_box -> gxy+assemble
// R12: hmma_box persistent (296 CTAs striding 392 tiles) to kill the wave tail.
// ---------------------------------------------------------------------------

#define N_ROIS 128
#define CEMB   512
#define HH     64
#define WW     96
#define KO     12544
#define NK     6272
#define GEO_SIZE 38535168ll

__device__ __nv_bfloat16 g_ehi[N_ROIS * 2048], g_elo[N_ROIS * 2048];
__device__ float g_ex   [HH * CEMB];
__device__ float g_ey   [WW * CEMB];
__device__ float g_partA[16 * N_ROIS * CEMB];
__device__ __nv_bfloat16 g_vhi[N_ROIS * CEMB], g_vlo[N_ROIS * CEMB];
__device__ __nv_bfloat16 g_ihi[160 * 256],     g_ilo[160 * 256];
__device__ __nv_bfloat16 g_bhi[NK * 256],      g_blo[NK * 256];

// ---------------------------------------------------------------------------
// helpers
// ---------------------------------------------------------------------------
__device__ __forceinline__ uint32_t smem_u32(const void* p) {
    uint32_t a;
    asm("{ .reg .u64 t; cvta.to.shared.u64 t, %1; cvt.u32.u64 %0, t; }"
        : "=r"(a) : "l"(p));
    return a;
}
#define SWZ128(x) ((x) ^ (((x) >> 3) & 0x70))

#define LDSM4(r, a) \
    asm volatile("ldmatrix.sync.aligned.m8n8.x4.shared.b16 {%0,%1,%2,%3}, [%4];" \
        : "=r"((r)[0]), "=r"((r)[1]), "=r"((r)[2]), "=r"((r)[3]) : "r"(a))

#define CP_ASYNC16(dst, src) \
    asm volatile("cp.async.cg.shared.global [%0], [%1], 16;" :: "r"(dst), "l"(src))
#define CP_COMMIT() asm volatile("cp.async.commit_group;")
#define CP_WAIT0()  asm volatile("cp.async.wait_group 0;" ::: "memory")

__device__ __forceinline__ void mma_bf16(float* d, const uint32_t* a, const uint32_t* b) {
    asm volatile("mma.sync.aligned.m16n8k16.row.col.f32.bf16.bf16.f32 "
        "{%0,%1,%2,%3}, {%4,%5,%6,%7}, {%8,%9}, {%0,%1,%2,%3};"
        : "+f"(d[0]), "+f"(d[1]), "+f"(d[2]), "+f"(d[3])
        : "r"(a[0]), "r"(a[1]), "r"(a[2]), "r"(a[3]), "r"(b[0]), "r"(b[1]));
}

__device__ __forceinline__ void split2(float a, float b, uint32_t& hi, uint32_t& lo) {
    __nv_bfloat16 ha = __float2bfloat16(a), hb = __float2bfloat16(b);
    __nv_bfloat16 la = __float2bfloat16(a - __bfloat162float(ha));
    __nv_bfloat16 lb = __float2bfloat16(b - __bfloat162float(hb));
    hi = (uint32_t)__bfloat16_as_ushort(ha) | ((uint32_t)__bfloat16_as_ushort(hb) << 16);
    lo = (uint32_t)__bfloat16_as_ushort(la) | ((uint32_t)__bfloat16_as_ushort(lb) << 16);
}

// ---------------------------------------------------------------------------
// embeddings (fp32 exp2f + sinf/cosf)
// ---------------------------------------------------------------------------
__device__ __forceinline__ float emb_f(float z, int i) {
    const float NEG_L2_1000_OVER_C = -9.965784284662087f / 512.0f;
    float e = (i < 256) ? (float)(2 * i + 1) : (float)(2 * (i - 256));
    float a = z * exp2f(e * NEG_L2_1000_OVER_C);
    return (i < 256) ? sinf(a) : cosf(a);
}

__global__ void emb_all_kernel(const float* __restrict__ rois) {
    int bid = blockIdx.x, tid = threadIdx.x;
    if (bid < 512) {
        int p = bid * 256 + tid;
        int idx = p * 2;
        int n = idx >> 11, d = idx & 2047;
        int j = d >> 9, i = d & 511;
        float z = rois[n * 5 + 1 + j];
        float v0 = emb_f(z, i), v1 = emb_f(z, i + 1);
        uint32_t hi, lo;
        split2(v0, v1, hi, lo);
        *(uint32_t*)(g_ehi + idx) = hi;
        *(uint32_t*)(g_elo + idx) = lo;
    } else {
        int idx = (bid - 512) * 256 + tid;
        int r = idx >> 9, i = idx & 511;
        float z = (float)(r < HH ? r : r - HH);
        float val = emb_f(z, i);
        if (r < HH) g_ex[r * CEMB + i] = val;
        else        g_ey[(r - HH) * CEMB + i] = val;
    }
}

// ---------------------------------------------------------------------------
// Fused: blocks 0..127 = hmma_v (split-K x16); blocks 128..147 = img SIMT GEMM
// ---------------------------------------------------------------------------
#define BOXB 49152
__global__ void __launch_bounds__(256)
hmma_v_img(const float* __restrict__ Vbox, const float* __restrict__ Wim)
{
    extern __shared__ __align__(1024) char smem[];
    int tid = threadIdx.x;

    if (blockIdx.x < 128) {
        uint32_t sbase = smem_u32(smem);
        int w = tid >> 5, l = tid & 31;
        int n0 = (blockIdx.x & 7) * 64;
        int kstart = (blockIdx.x >> 3) * 128;
        int wm = (w >> 1) * 32, wn = (w & 1) * 32;

        uint4 aR[8];
        float4 bRf[4];
        auto loadg = [&](int t) {
            int k0 = kstart + t * 64;
#pragma unroll
            for (int i = 0; i < 4; i++) {
                int s = tid + i * 256, r = s >> 3, c = s & 7;
                size_t eo = (size_t)r * 2048 + k0 + c * 8;
                aR[i]     = *(const uint4*)(g_ehi + eo);
                aR[i + 4] = *(const uint4*)(g_elo + eo);
            }
#pragma unroll
            for (int i = 0; i < 2; i++) {
                int s = tid + i * 256, r = s >> 3, c = s & 7;
                const float* src = Vbox + (size_t)(n0 + r) * 2048 + k0 + c * 8;
                bRf[2 * i]     = *(const float4*)src;
                bRf[2 * i + 1] = *(const float4*)(src + 4);
            }
        };
        auto storeb = [&](int buf) {
            char* base = smem + buf * BOXB;
#pragma unroll
            for (int i = 0; i < 4; i++) {
                int s = tid + i * 256, r = s >> 3, c = s & 7;
                uint32_t off = SWZ128((uint32_t)(r * 128 + c * 16));
                *(uint4*)(base + off)         = aR[i];
                *(uint4*)(base + 16384 + off) = aR[i + 4];
            }
#pragma unroll
            for (int i = 0; i < 2; i++) {
                int s = tid + i * 256, r = s >> 3, c = s & 7;
                float fv[8] = {bRf[2*i].x, bRf[2*i].y, bRf[2*i].z, bRf[2*i].w,
                               bRf[2*i+1].x, bRf[2*i+1].y, bRf[2*i+1].z, bRf[2*i+1].w};
                uint4 h4, l4;
                split2(fv[0], fv[1], h4.x, l4.x); split2(fv[2], fv[3], h4.y, l4.y);
                split2(fv[4], fv[5], h4.z, l4.z); split2(fv[6], fv[7], h4.w, l4.w);
                uint32_t off = SWZ128((uint32_t)(r * 128 + c * 16));
                *(uint4*)(base + 32768 + off) = h4;
                *(uint4*)(base + 40960 + off) = l4;
            }
        };

        float acc[2][4][4];
#pragma unroll
        for (int s = 0; s < 2; s++)
#pragma unroll
            for (int j = 0; j < 4; j++)
#pragma unroll
                for (int q = 0; q < 4; q++) acc[s][j][q] = 0.f;

        loadg(0); storeb(0);
        __syncthreads();

        for (int t = 0; t < 2; t++) {
            int buf = t & 1;
            if (t + 1 < 2) loadg(t + 1);
            uint32_t B0 = sbase + buf * BOXB;
#pragma unroll
            for (int kk = 0; kk < 4; kk++) {
                uint32_t ah[2][4], al[2][4];
#pragma unroll
                for (int s = 0; s < 2; s++) {
                    int row = wm + s * 16 + (l & 15);
                    int ch = kk * 2 + (l >> 4);
                    uint32_t off = SWZ128((uint32_t)(row * 128 + ch * 16));
                    LDSM4(ah[s], B0 + off);
                    LDSM4(al[s], B0 + 16384 + off);
                }
#pragma unroll
                for (int p = 0; p < 2; p++) {
                    int nrow = wn + p * 16 + (l & 7) + ((l >> 4) << 3);
                    int ch = kk * 2 + ((l >> 3) & 1);
                    uint32_t off = SWZ128((uint32_t)(nrow * 128 + ch * 16));
                    uint32_t bh[4], bl[4];
                    LDSM4(bh, B0 + 32768 + off);
                    LDSM4(bl, B0 + 40960 + off);
#pragma unroll
                    for (int s = 0; s < 2; s++) {
                        mma_bf16(acc[s][2*p],     ah[s], bh);
                        mma_bf16(acc[s][2*p],     ah[s], bl);
                        mma_bf16(acc[s][2*p],     al[s], bh);
                        mma_bf16(acc[s][2*p + 1], ah[s], bh + 2);
                        mma_bf16(acc[s][2*p + 1], ah[s], bl + 2);
                        mma_bf16(acc[s][2*p + 1], al[s], bh + 2);
                    }
                }
            }
            if (t + 1 < 2) {
                storeb(buf ^ 1);
                __syncthreads();
            }
        }

        float* Cp = g_partA + (size_t)(blockIdx.x >> 3) * (N_ROIS * CEMB);
#pragma unroll
        for (int s = 0; s < 2; s++) {
            int m = wm + s * 16 + (l >> 2);
#pragma unroll
            for (int j = 0; j < 4; j++) {
                int o = n0 + wn + j * 8 + (l & 3) * 2;
                *(float2*)(Cp + (size_t)m * 512 + o) = make_float2(acc[s][j][0], acc[s][j][1]);
                *(float2*)(Cp + (size_t)(m + 8) * 512 + o) = make_float2(acc[s][j][2], acc[s][j][3]);
            }
        }
    } else {
        // img: [160,256] = [ex;ey] @ W_im halves^T  (SIMT 32x64, K=512)
        float* As = (float*)smem;
        float* Bs = (float*)(smem + 8192);
        int b = blockIdx.x - 128;
        int m0 = (b % 5) * 32;
        int n0 = (b / 5) * 64;
        const float* Abase = (m0 < HH) ? g_ex + (size_t)m0 * CEMB
                                       : g_ey + (size_t)(m0 - HH) * CEMB;
        int boff = (m0 < HH) ? 0 : 512;
        int tx = tid & 15, ty = tid >> 4;

        float4 aR;
        float4 bR[2];
        auto loadA = [&](int t) {
            int r = tid >> 3, kq = (tid & 7) * 4;
            aR = *(const float4*)(Abase + (size_t)r * CEMB + t * 32 + kq);
        };
        auto loadB = [&](int t) {
#pragma unroll
            for (int i = 0; i < 2; i++) {
                int f = tid + i * 256, r = f >> 3, kq = (f & 7) * 4;
                bR[i] = *(const float4*)(Wim + (size_t)(n0 + r) * 1024 + boff + t * 32 + kq);
            }
        };
        auto storeAB = [&](int buf) {
            int r = tid >> 3, kq = (tid & 7) * 4;
            As[buf * 1024 + (kq + 0) * 32 + r] = aR.x;
            As[buf * 1024 + (kq + 1) * 32 + r] = aR.y;
            As[buf * 1024 + (kq + 2) * 32 + r] = aR.z;
            As[buf * 1024 + (kq + 3) * 32 + r] = aR.w;
#pragma unroll
            for (int i = 0; i < 2; i++) {
                int f = tid + i * 256, rr = f >> 3, kq2 = (f & 7) * 4;
                Bs[buf * 2048 + (kq2 + 0) * 64 + rr] = bR[i].x;
                Bs[buf * 2048 + (kq2 + 1) * 64 + rr] = bR[i].y;
                Bs[buf * 2048 + (kq2 + 2) * 64 + rr] = bR[i].z;
                Bs[buf * 2048 + (kq2 + 3) * 64 + rr] = bR[i].w;
            }
        };

        float acc[2][4];
#pragma unroll
        for (int i = 0; i < 2; i++)
#pragma unroll
            for (int j = 0; j < 4; j++) acc[i][j] = 0.f;

        loadA(0); loadB(0); storeAB(0);
        __syncthreads();

        for (int t = 0; t < 16; t++) {
            int buf = t & 1;
            if (t + 1 < 16) { loadA(t + 1); loadB(t + 1); }
#pragma unroll
            for (int kk = 0; kk < 32; kk++) {
                float2 a2 = *(const float2*)&As[buf * 1024 + kk * 32 + ty * 2];
                float4 b4 = *(const float4*)&Bs[buf * 2048 + kk * 64 + tx * 4];
                acc[0][0] += a2.x * b4.x; acc[0][1] += a2.x * b4.y;
                acc[0][2] += a2.x * b4.z; acc[0][3] += a2.x * b4.w;
                acc[1][0] += a2.y * b4.x; acc[1][1] += a2.y * b4.y;
                acc[1][2] += a2.y * b4.z; acc[1][3] += a2.y * b4.w;
            }
            if (t + 1 < 16) {
                storeAB(buf ^ 1);
                __syncthreads();
            }
        }

#pragma unroll
        for (int i = 0; i < 2; i++) {
            int row = m0 + ty * 2 + i;
            int col = n0 + tx * 4;
            uint32_t h0, l0, h1, l1;
            split2(acc[i][0], acc[i][1], h0, l0);
            split2(acc[i][2], acc[i][3], h1, l1);
            *(uint32_t*)(g_ihi + (size_t)row * 256 + col)     = h0;
            *(uint32_t*)(g_ihi + (size_t)row * 256 + col + 2) = h1;
            *(uint32_t*)(g_ilo + (size_t)row * 256 + col)     = l0;
            *(uint32_t*)(g_ilo + (size_t)row * 256 + col + 2) = l1;
        }
    }
}

// vectorized split-K reduction for v
__global__ void reduce_v_kernel() {
    int q = blockIdx.x * blockDim.x + threadIdx.x;
    if (q >= 16384) return;
    float4 s = *(const float4*)(g_partA + (size_t)q * 4);
#pragma unroll
    for (int p = 1; p < 16; p++) {
        float4 t = *(const float4*)(g_partA + (size_t)p * 65536 + (size_t)q * 4);
        s.x += t.x; s.y += t.y; s.z += t.z; s.w += t.w;
    }
    uint32_t h0, l0, h1, l1;
    split2(s.x, s.y, h0, l0);
    split2(s.z, s.w, h1, l1);
    *(uint32_t*)(g_vhi + (size_t)q * 4)     = h0;
    *(uint32_t*)(g_vhi + (size_t)q * 4 + 2) = h1;
    *(uint32_t*)(g_vlo + (size_t)q * 4)     = l0;
    *(uint32_t*)(g_vlo + (size_t)q * 4 + 2) = l1;
}

// ---------------------------------------------------------------------------
// HMMA box GEMM: C[128, 12544] = v @ W_box^T, K=512.
// PERSISTENT: 296 CTAs (2/SM) stride over 392 tiles of 128M x 32N.
// A (bf16 hi/lo) via cp.async (L2-resident); B (fp32) via regs + split.
// buf (40960B): Ahi 16K | Alo 16K | Bhi 4K | Blo 4K.  2 bufs = 80K.
// ---------------------------------------------------------------------------
#define BOXB2 40960
#define BOX_TILES 392
#define BOX_GRID  296
__global__ void __launch_bounds__(256, 2)
hmma_box(const float* __restrict__ Wbox)
{
    extern __shared__ __align__(1024) char smem[];
    uint32_t sbase = smem_u32(smem);
    int tid = threadIdx.x, w = tid >> 5, l = tid & 31;
    int wm = (w >> 1) * 32, wn = (w & 1) * 16;

    for (int tile = blockIdx.x; tile < BOX_TILES; tile += BOX_GRID) {
        int n0 = tile * 32;
        int kcta = n0 >> 8, o0 = n0 & 255;

        auto issueA = [&](int t, int buf) {
            uint32_t base = sbase + buf * BOXB2;
            int k0 = t * 64;
#pragma unroll
            for (int i = 0; i < 4; i++) {
                int s = tid + i * 256, r = s >> 3, c = s & 7;
                size_t eo = (size_t)r * 512 + k0 + c * 8;
                uint32_t off = SWZ128((uint32_t)(r * 128 + c * 16));
                CP_ASYNC16(base + off,         g_vhi + eo);
                CP_ASYNC16(base + 16384 + off, g_vlo + eo);
            }
            CP_COMMIT();
        };

        float4 bRf[2];
        auto loadB = [&](int t) {
            int r = tid >> 3, c = tid & 7;
            const float* src = Wbox + (size_t)(n0 + r) * 512 + t * 64 + c * 8;
            bRf[0] = *(const float4*)src;
            bRf[1] = *(const float4*)(src + 4);
        };
        auto storeB = [&](int buf) {
            char* base = smem + buf * BOXB2;
            int r = tid >> 3, c = tid & 7;
            float fv[8] = {bRf[0].x, bRf[0].y, bRf[0].z, bRf[0].w,
                           bRf[1].x, bRf[1].y, bRf[1].z, bRf[1].w};
            uint4 h4, l4;
            split2(fv[0], fv[1], h4.x, l4.x); split2(fv[2], fv[3], h4.y, l4.y);
            split2(fv[4], fv[5], h4.z, l4.z); split2(fv[6], fv[7], h4.w, l4.w);
            uint32_t off = SWZ128((uint32_t)(r * 128 + c * 16));
            *(uint4*)(base + 32768 + off) = h4;
            *(uint4*)(base + 36864 + off) = l4;
        };

        float acc[2][2][4];
#pragma unroll
        for (int s = 0; s < 2; s++)
#pragma unroll
            for (int j = 0; j < 2; j++)
#pragma unroll
                for (int q = 0; q < 4; q++) acc[s][j][q] = 0.f;

        __syncthreads();       // smem from previous tile fully consumed
        issueA(0, 0);
        loadB(0); storeB(0);
        CP_WAIT0();
        __syncthreads();

        for (int t = 0; t < 8; t++) {
            int buf = t & 1;
            if (t + 1 < 8) { issueA(t + 1, buf ^ 1); loadB(t + 1); }

            uint32_t B0 = sbase + buf * BOXB2;
#pragma unroll
            for (int kk = 0; kk < 4; kk++) {
                uint32_t ah[2][4], al[2][4];
#pragma unroll
                for (int s = 0; s < 2; s++) {
                    int row = wm + s * 16 + (l & 15);
                    int ch = kk * 2 + (l >> 4);
                    uint32_t off = SWZ128((uint32_t)(row * 128 + ch * 16));
                    LDSM4(ah[s], B0 + off);
                    LDSM4(al[s], B0 + 16384 + off);
                }
                int nrow = wn + (l & 7) + ((l >> 4) << 3);
                int ch = kk * 2 + ((l >> 3) & 1);
                uint32_t off = SWZ128((uint32_t)(nrow * 128 + ch * 16));
                uint32_t bh[4], bl[4];
                LDSM4(bh, B0 + 32768 + off);
                LDSM4(bl, B0 + 36864 + off);
#pragma unroll
                for (int s = 0; s < 2; s++) {
                    mma_bf16(acc[s][0], ah[s], bh);
                    mma_bf16(acc[s][0], ah[s], bl);
                    mma_bf16(acc[s][0], al[s], bh);
                    mma_bf16(acc[s][1], ah[s], bh + 2);
                    mma_bf16(acc[s][1], ah[s], bl + 2);
                    mma_bf16(acc[s][1], al[s], bh + 2);
                }
            }
            if (t + 1 < 8) {
                storeB(buf ^ 1);
                CP_WAIT0();
                __syncthreads();
            }
        }

        // epilogue -> g_bhi/g_blo[(m*49 + kcta)*256 + o]
#pragma unroll
        for (int s = 0; s < 2; s++) {
            int m = wm + s * 16 + (l >> 2);
#pragma unroll
            for (int j = 0; j < 2; j++) {
                int o = o0 + wn + j * 8 + (l & 3) * 2;
                uint32_t hi, lo;
                split2(acc[s][j][0], acc[s][j][1], hi, lo);
                size_t b0 = (size_t)(m * 49 + kcta) * 256 + o;
                *(uint32_t*)(g_bhi + b0) = hi;
                *(uint32_t*)(g_blo + b0) = lo;
                split2(acc[s][j][2], acc[s][j][3], hi, lo);
                size_t b1 = (size_t)((m + 8) * 49 + kcta) * 256 + o;
                *(uint32_t*)(g_bhi + b1) = hi;
                *(uint32_t*)(g_blo + b1) = lo;
            }
        }
    }
}

// ---------------------------------------------------------------------------
// HMMA Gxy GEMM + fused assemble + indices: 98 blocks 64x160, K=256.
// ---------------------------------------------------------------------------
#define GXYB 57344
__global__ void __launch_bounds__(256)
hmma_gxy(float* __restrict__ outg, const float* __restrict__ rois,
         void* d_out, int mode)
{
    extern __shared__ __align__(1024) char smem[];
    uint32_t sbase = smem_u32(smem);
    int tid = threadIdx.x, w = tid >> 5, l = tid & 31;
    int m0 = blockIdx.x * 64;
    int wm = (w >> 1) * 16, wn = (w & 1) * 80;

    if (mode && blockIdx.x == 0 && tid < N_ROIS) {
        long long v = (long long)rois[tid * 5];
        if (mode == 1) ((float*)d_out)[tid] = (float)v;
        else           ((long long*)d_out)[tid] = v;
    }

    uint4 aR[4], bR[10];
    auto loadg = [&](int t) {
        int k0 = t * 64;
#pragma unroll
        for (int i = 0; i < 2; i++) {
            int s = tid + i * 256, r = s >> 3, c = s & 7;
            size_t eo = (size_t)(m0 + r) * 256 + k0 + c * 8;
            aR[i]     = *(const uint4*)(g_bhi + eo);
            aR[i + 2] = *(const uint4*)(g_blo + eo);
        }
#pragma unroll
        for (int i = 0; i < 5; i++) {
            int s = tid + i * 256, r = s >> 3, c = s & 7;
            size_t eo = (size_t)r * 256 + k0 + c * 8;
            bR[i]     = *(const uint4*)(g_ihi + eo);
            bR[i + 5] = *(const uint4*)(g_ilo + eo);
        }
    };
    auto storeb = [&](int buf) {
        char* base = smem + buf * GXYB;
#pragma unroll
        for (int i = 0; i < 2; i++) {
            int s = tid + i * 256, r = s >> 3, c = s & 7;
            uint32_t off = SWZ128((uint32_t)(r * 128 + c * 16));
            *(uint4*)(base + off)        = aR[i];
            *(uint4*)(base + 8192 + off) = aR[i + 2];
        }
#pragma unroll
        for (int i = 0; i < 5; i++) {
            int s = tid + i * 256, r = s >> 3, c = s & 7;
            uint32_t off = SWZ128((uint32_t)(r * 128 + c * 16));
            *(uint4*)(base + 16384 + off) = bR[i];
            *(uint4*)(base + 36864 + off) = bR[i + 5];
        }
    };

    float acc[10][4];
#pragma unroll
    for (int j = 0; j < 10; j++)
#pragma unroll
        for (int q = 0; q < 4; q++) acc[j][q] = 0.f;

    loadg(0); storeb(0);
    __syncthreads();

    for (int t = 0; t < 4; t++) {
        int buf = t & 1;
        if (t + 1 < 4) loadg(t + 1);
        uint32_t B0 = sbase + buf * GXYB;
#pragma unroll
        for (int kk = 0; kk < 4; kk++) {
            uint32_t ah[4], al[4];
            {
                int row = wm + (l & 15);
                int ch = kk * 2 + (l >> 4);
                uint32_t off = SWZ128((uint32_t)(row * 128 + ch * 16));
                LDSM4(ah, B0 + off);
                LDSM4(al, B0 + 8192 + off);
            }
#pragma unroll
            for (int p = 0; p < 5; p++) {
                int nrow = wn + p * 16 + (l & 7) + ((l >> 4) << 3);
                int ch = kk * 2 + ((l >> 3) & 1);
                uint32_t off = SWZ128((uint32_t)(nrow * 128 + ch * 16));
                uint32_t bh[4], bl[4];
                LDSM4(bh, B0 + 16384 + off);
                LDSM4(bl, B0 + 36864 + off);
                mma_bf16(acc[2*p],     ah, bh);
                mma_bf16(acc[2*p],     ah, bl);
                mma_bf16(acc[2*p],     al, bh);
                mma_bf16(acc[2*p + 1], ah, bh + 2);
                mma_bf16(acc[2*p + 1], ah, bl + 2);
                mma_bf16(acc[2*p + 1], al, bh + 2);
            }
        }
        if (t + 1 < 4) {
            storeb(buf ^ 1);
            __syncthreads();
        }
    }

    // fused assemble
    __syncthreads();
    float* sxy = (float*)smem;
    {
        int row = wm + (l >> 2);
#pragma unroll
        for (int j = 0; j < 10; j++) {
            int col = wn + j * 8 + (l & 3) * 2;
            sxy[row * 160 + col]           = acc[j][0];
            sxy[row * 160 + col + 1]       = acc[j][1];
            sxy[(row + 8) * 160 + col]     = acc[j][2];
            sxy[(row + 8) * 160 + col + 1] = acc[j][3];
        }
    }
    __syncthreads();

    for (int idx = tid; idx < 64 * 1536; idx += 256) {
        int nkl = idx / 1536, rem = idx - nkl * 1536;
        int h = rem / 24, w4 = (rem - h * 24) * 4;
        const float* rowp = sxy + nkl * 160;
        float gx = rowp[h];
        float4 v = make_float4(gx + rowp[64 + w4 + 0], gx + rowp[64 + w4 + 1],
                               gx + rowp[64 + w4 + 2], gx + rowp[64 + w4 + 3]);
        *(float4*)(outg + (size_t)(m0 + nkl) * 6144 + h * 96 + w4) = v;
    }
}

// ---------------------------------------------------------------------------
extern "C" void kernel_launch(void* const* d_in, const int* in_sizes, int n_in,
                              void* d_out, int out_size)
{
    const float* rois  = (const float*)d_in[1];
    const float* V_box = (const float*)d_in[2];
    const float* W_box = (const float*)d_in[3];
    const float* W_im  = (const float*)d_in[4];

    cudaFuncSetAttribute(hmma_v_img, cudaFuncAttributeMaxDynamicSharedMemorySize, 2 * BOXB);
    cudaFuncSetAttribute(hmma_box,   cudaFuncAttributeMaxDynamicSharedMemorySize, 2 * BOXB2);
    cudaFuncSetAttribute(hmma_gxy,   cudaFuncAttributeMaxDynamicSharedMemorySize, 2 * GXYB);

    long long extra = (long long)out_size - GEO_SIZE;
    int mode = (extra == 128) ? 1 : (extra == 256 ? 2 : 0);
    float* outg = (float*)d_out + (extra > 0 ? extra : 0);

    // 1) all embeddings
    emb_all_kernel<<<832, 256>>>(rois);

    // 2) fused: v split-K HMMA (128 blocks) + img SIMT GEMM (20 blocks)
    hmma_v_img<<<148, 256, 2 * BOXB>>>(V_box, W_im);

    // 3) reduce v partials -> bf16 hi/lo
    reduce_v_kernel<<<64, 256>>>();

    // 4) box = v @ W_box^T  (HMMA bf16x3, persistent 296 CTAs over 392 tiles)
    hmma_box<<<BOX_GRID, 256, 2 * BOXB2>>>(W_box);

    // 5) Gxy + fused assemble + indices
    hmma_gxy<<<98, 256, 2 * GXYB>>>(outg, rois, d_out, mode);
}